// round 8
// baseline (speedup 1.0000x reference)
#include <cuda_runtime.h>
#include <math.h>

// Problem constants
#define B_   64
#define S_   4096
#define ENC_ 512
#define DEC_ 512

#define GPB   37                  // CTAs per batch (2368 = 16*148 total, single wave)
#define NWARP 2                   // warps per CTA
#define NSLOT (B_ * GPB)

// ---- scratch (no allocations allowed; __device__ globals) ----
__device__ float g_sub[B_ * ENC_];          // dec @ W^T            (128 KB)
__device__ float g_logits[B_ * S_];         // raw attention logits (1 MB)
__device__ float g_pm[NSLOT];               // per-slot running max
__device__ float g_pl[NSLOT];               // per-slot running denom
__device__ float g_pacc[NSLOT * ENC_];      // per-slot weighted-sum vec (4.85 MB)
__device__ unsigned g_cnt[B_];              // last-CTA-done tickets (reset by sub_kernel)

// ============================================================
// Kernel 1: sub[b,e] = sum_d dec[b,d] * W[e,d]     (tiny GEMV)
// R2 version (best measured). grid = (8, 64), block = 256.
// Also resets g_cnt[b] (runs strictly before pass1 in stream order).
// ============================================================
__global__ __launch_bounds__(256) void sub_kernel(const float* __restrict__ dec,
                                                  const float* __restrict__ W) {
    const int et   = blockIdx.x;          // e-tile of 64
    const int b    = blockIdx.y;
    const int tid  = threadIdx.x;
    const int w    = tid >> 5;
    const int lane = tid & 31;

    if (et == 0 && tid == 0) g_cnt[b] = 0;   // reset ticket for this batch

    __shared__ float dsm[DEC_];
    for (int i = tid; i < DEC_; i += 256) dsm[i] = dec[b * DEC_ + i];
    __syncthreads();

    const float4* d4 = (const float4*)dsm;
    float4 dv[4];
#pragma unroll
    for (int j = 0; j < 4; j++) dv[j] = d4[lane + 32 * j];

    const int e0 = et * 64 + w * 8;       // warp handles e0 .. e0+7
#pragma unroll
    for (int i = 0; i < 8; i++) {
        const int e = e0 + i;
        const float4* Wr = (const float4*)(W + (size_t)e * DEC_);
        float s = 0.f;
#pragma unroll
        for (int j = 0; j < 4; j++) {
            float4 wv = Wr[lane + 32 * j];
            s += wv.x * dv[j].x + wv.y * dv[j].y + wv.z * dv[j].z + wv.w * dv[j].w;
        }
#pragma unroll
        for (int o = 16; o > 0; o >>= 1) s += __shfl_xor_sync(0xffffffffu, s, o);
        if (lane == 0) g_sub[b * ENC_ + e] = s;
    }
}

// ============================================================
// Kernel 2: streaming pass — logits + online softmax + fused finalize.
// grid = (GPB, B_) = (37, 64) = 2368 CTAs, block = 64 (2 warps).
// 16 CTAs/SM * 148 SMs = 2368: EVERY SM carries exactly 16 equal CTAs
// -> per-SM byte balance ~1% (vs 33% skew at 512 CTAs / 4-per-SM).
// Rows assigned by stride GPB: CTA `slice` owns rows slice + 37k.
// Inner loop identical to proven R2 loop.
// ============================================================
__global__ __launch_bounds__(64, 16) void attn_pass1(const float* __restrict__ enc,
                                                     float* __restrict__ out) {
    const int slice = blockIdx.x;         // 0..36
    const int b     = blockIdx.y;
    const int tid   = threadIdx.x;        // 0..63
    const int w     = tid >> 5;           // 0..1
    const int lane  = tid & 31;

    __shared__ float subsm[ENC_];
    __shared__ float accsm[NWARP][ENC_];  // 4 KB
    __shared__ float msm[NWARP], lsm[NWARP];
    __shared__ bool  is_last;

    for (int i = tid; i < ENC_; i += 64) subsm[i] = g_sub[b * ENC_ + i];
    __syncthreads();

    // cache this lane's 16-float slice of sub in registers
    float4 subr[4];
    const float4* sub4 = (const float4*)subsm;
#pragma unroll
    for (int j = 0; j < 4; j++) subr[j] = sub4[lane + 32 * j];

    float m = -1e30f;
    float l = 0.f;
    float4 acc[4];
#pragma unroll
    for (int j = 0; j < 4; j++) acc[j] = make_float4(0.f, 0.f, 0.f, 0.f);

    const float* encb = enc + (size_t)b * S_ * ENC_;

    // warp w of this CTA owns rows s = slice + GPB*(w + 2k)
    for (int s = slice + GPB * w; s < S_; s += GPB * NWARP) {
        const float4* er = (const float4*)(encb + (size_t)s * ENC_);

        float4 ev[4];
#pragma unroll
        for (int j = 0; j < 4; j++) ev[j] = __ldcs(&er[lane + 32 * j]);  // 4 indep loads

        float dot = 0.f;
#pragma unroll
        for (int j = 0; j < 4; j++) {
            dot += ev[j].x * subr[j].x + ev[j].y * subr[j].y +
                   ev[j].z * subr[j].z + ev[j].w * subr[j].w;
        }
#pragma unroll
        for (int o = 16; o > 0; o >>= 1) dot += __shfl_xor_sync(0xffffffffu, dot, o);

        if (lane == 0) g_logits[b * S_ + s] = dot;

        // online softmax update (warp-uniform)
        const float mn    = fmaxf(m, dot);
        const float scale = __expf(m - mn);
        const float p     = __expf(dot - mn);
        l = l * scale + p;
#pragma unroll
        for (int j = 0; j < 4; j++) {
            acc[j].x = acc[j].x * scale + p * ev[j].x;
            acc[j].y = acc[j].y * scale + p * ev[j].y;
            acc[j].z = acc[j].z * scale + p * ev[j].z;
            acc[j].w = acc[j].w * scale + p * ev[j].w;
        }
        m = mn;
    }

    // spill warp state to smem
    float4* arow = (float4*)accsm[w];
#pragma unroll
    for (int j = 0; j < 4; j++) arow[lane + 32 * j] = acc[j];
    if (lane == 0) { msm[w] = m; lsm[w] = l; }
    __syncthreads();

    // 2-warp merge (every thread redundantly computes M,L — cheap)
    const float M = fmaxf(msm[0], msm[1]);
    const float w0 = __expf(msm[0] - M);
    const float w1 = __expf(msm[1] - M);
    const float L = lsm[0] * w0 + lsm[1] * w1;

    const int cid = b * GPB + slice;
    if (tid == 0) { g_pm[cid] = M; g_pl[cid] = L; }

    for (int e = tid; e < ENC_; e += 64)
        g_pacc[(size_t)cid * ENC_ + e] = accsm[0][e] * w0 + accsm[1][e] * w1;

    // ---- last-CTA-done: final CTA of batch b finalizes ----
    __threadfence();
    __syncthreads();
    if (tid == 0) {
        unsigned r = atomicAdd(&g_cnt[b], 1u);
        is_last = (r == GPB - 1);
    }
    __syncthreads();
    if (!is_last) return;

    __threadfence();
    float Mg = -1e30f;
#pragma unroll
    for (int cc = 0; cc < GPB; cc++) Mg = fmaxf(Mg, g_pm[b * GPB + cc]);
    float Lg = 0.f;
    float wg[GPB];
#pragma unroll
    for (int cc = 0; cc < GPB; cc++) {
        wg[cc] = __expf(g_pm[b * GPB + cc] - Mg);
        Lg += g_pl[b * GPB + cc] * wg[cc];
    }
    const float invL = 1.f / Lg;

    const float* lg = g_logits + b * S_;
    float* attn_out = out + (size_t)b * S_;
    for (int s = tid; s < S_; s += 64)
        attn_out[s] = __expf(lg[s] - Mg) * invL;

    float* sum_out = out + (size_t)B_ * S_ + (size_t)b * ENC_;
    for (int e = tid; e < ENC_; e += 64) {
        float a = 0.f;
#pragma unroll
        for (int cc = 0; cc < GPB; cc++)
            a += g_pacc[(size_t)(b * GPB + cc) * ENC_ + e] * wg[cc];
        sum_out[e] = a * invL;
    }
}

// ============================================================
extern "C" void kernel_launch(void* const* d_in, const int* in_sizes, int n_in,
                              void* d_out, int out_size) {
    const float* dec = (const float*)d_in[0];  // [64,1,512]
    const float* enc = (const float*)d_in[1];  // [64,4096,512]
    const float* W   = (const float*)d_in[2];  // [512,512]
    float* out = (float*)d_out;

    sub_kernel<<<dim3(ENC_ / 64, B_), 256>>>(dec, W);
    attn_pass1<<<dim3(GPB, B_), 64>>>(enc, out);
}

// round 9
// speedup vs baseline: 1.2719x; 1.2719x over previous
#include <cuda_runtime.h>
#include <math.h>

// Problem constants
#define B_   64
#define S_   4096
#define ENC_ 512
#define DEC_ 512

#define NCTA   592                 // 148 SMs * 4 CTAs  (one perfectly even wave)
#define TROWS  443                 // rows per CTA (592*443 >= 262144)
#define GROWS  (B_ * S_)           // 262144 global rows
#define MAXSLOT 16                 // max partial-slots per batch (need <= 11)

// ---- scratch (no allocations allowed; __device__ globals) ----
__device__ float g_sub[B_ * ENC_];             // dec @ W^T             (128 KB)
__device__ float g_logits[B_ * S_];            // raw attention logits  (1 MB)
__device__ float g_pm[B_ * MAXSLOT];           // per-slot max
__device__ float g_pl[B_ * MAXSLOT];           // per-slot denom
__device__ float g_pacc[B_ * MAXSLOT * ENC_];  // per-slot weighted sums (2 MB)
__device__ unsigned g_ns[B_];                  // slots used per batch
__device__ unsigned g_cnt[B_];                 // rows completed per batch

// ============================================================
// Kernel 1: sub[b,e] = sum_d dec[b,d] * W[e,d]   (R2 version, best measured)
// grid = (8, 64), block = 256. Also resets counters (runs before pass1).
// ============================================================
__global__ __launch_bounds__(256) void sub_kernel(const float* __restrict__ dec,
                                                  const float* __restrict__ W) {
    const int et   = blockIdx.x;
    const int b    = blockIdx.y;
    const int tid  = threadIdx.x;
    const int w    = tid >> 5;
    const int lane = tid & 31;

    if (et == 0 && tid == 0) { g_cnt[b] = 0; g_ns[b] = 0; }

    __shared__ float dsm[DEC_];
    for (int i = tid; i < DEC_; i += 256) dsm[i] = dec[b * DEC_ + i];
    __syncthreads();

    const float4* d4 = (const float4*)dsm;
    float4 dv[4];
#pragma unroll
    for (int j = 0; j < 4; j++) dv[j] = d4[lane + 32 * j];

    const int e0 = et * 64 + w * 8;
#pragma unroll
    for (int i = 0; i < 8; i++) {
        const int e = e0 + i;
        const float4* Wr = (const float4*)(W + (size_t)e * DEC_);
        float s = 0.f;
#pragma unroll
        for (int j = 0; j < 4; j++) {
            float4 wv = Wr[lane + 32 * j];
            s += wv.x * dv[j].x + wv.y * dv[j].y + wv.z * dv[j].z + wv.w * dv[j].w;
        }
#pragma unroll
        for (int o = 16; o > 0; o >>= 1) s += __shfl_xor_sync(0xffffffffu, s, o);
        if (lane == 0) g_sub[b * ENC_ + e] = s;
    }
}

// ============================================================
// Kernel 2: balanced streaming pass + fused finalize.
// grid = 592 flat CTAs, block = 256 (8 warps).
// CTA k owns contiguous global rows [k*443, min((k+1)*443, 262144));
// crosses at most one batch boundary. Inner loop = proven R2 loop.
// Per batch-segment: flush (M,L,pacc) to an atomically-allocated slot,
// ticket rows done; the CTA that completes 4096 rows finalizes batch.
// ============================================================
__global__ __launch_bounds__(256) void attn_pass1(const float* __restrict__ enc,
                                                  float* __restrict__ out) {
    const int tid  = threadIdx.x;
    const int w    = tid >> 5;
    const int lane = tid & 31;

    const int row0 = blockIdx.x * TROWS;
    const int row1 = min(row0 + TROWS, GROWS);

    __shared__ float subsm[ENC_];
    __shared__ float accsm[8][ENC_];     // 16 KB
    __shared__ float msm[8], lsm[8];
    __shared__ int   slot_sh;
    __shared__ bool  is_last;

    int row = row0;
    while (row < row1) {
        const int b      = row >> 12;                 // row / 4096
        const int segend = min(row1, (b + 1) << 12);
        const int nrows  = segend - row;

        __syncthreads();                              // protect subsm/accsm reuse
        for (int i = tid; i < ENC_; i += 256) subsm[i] = g_sub[b * ENC_ + i];
        __syncthreads();

        float4 subr[4];
        const float4* sub4 = (const float4*)subsm;
#pragma unroll
        for (int j = 0; j < 4; j++) subr[j] = sub4[lane + 32 * j];

        float m = -1e30f;
        float l = 0.f;
        float4 acc[4];
#pragma unroll
        for (int j = 0; j < 4; j++) acc[j] = make_float4(0.f, 0.f, 0.f, 0.f);

        const float* encb = enc + (size_t)b * S_ * ENC_;

        for (int s = row + w; s < segend; s += 8) {
            const int sl = s - (b << 12);             // row within batch
            const float4* er = (const float4*)(encb + (size_t)sl * ENC_);

            float4 ev[4];
#pragma unroll
            for (int j = 0; j < 4; j++) ev[j] = __ldcs(&er[lane + 32 * j]);

            float dot = 0.f;
#pragma unroll
            for (int j = 0; j < 4; j++) {
                dot += ev[j].x * subr[j].x + ev[j].y * subr[j].y +
                       ev[j].z * subr[j].z + ev[j].w * subr[j].w;
            }
#pragma unroll
            for (int o = 16; o > 0; o >>= 1) dot += __shfl_xor_sync(0xffffffffu, dot, o);

            if (lane == 0) g_logits[b * S_ + sl] = dot;

            const float mn    = fmaxf(m, dot);
            const float scale = __expf(m - mn);
            const float p     = __expf(dot - mn);
            l = l * scale + p;
#pragma unroll
            for (int j = 0; j < 4; j++) {
                acc[j].x = acc[j].x * scale + p * ev[j].x;
                acc[j].y = acc[j].y * scale + p * ev[j].y;
                acc[j].z = acc[j].z * scale + p * ev[j].z;
                acc[j].w = acc[j].w * scale + p * ev[j].w;
            }
            m = mn;
        }

        // spill warp state to smem
        float4* arow = (float4*)accsm[w];
#pragma unroll
        for (int j = 0; j < 4; j++) arow[lane + 32 * j] = acc[j];
        if (lane == 0) { msm[w] = m; lsm[w] = l; }
        __syncthreads();

        // block merge
        float M = -1e30f;
#pragma unroll
        for (int ww = 0; ww < 8; ww++) M = fmaxf(M, msm[ww]);
        float L = 0.f;
        float wts[8];
#pragma unroll
        for (int ww = 0; ww < 8; ww++) {
            wts[ww] = __expf(msm[ww] - M);
            L += lsm[ww] * wts[ww];
        }

        // flush to a dynamically-allocated slot for batch b
        if (tid == 0) slot_sh = (int)atomicAdd(&g_ns[b], 1u);
        __syncthreads();
        const int sid = b * MAXSLOT + slot_sh;
        if (tid == 0) { g_pm[sid] = M; g_pl[sid] = L; }
        for (int e = tid; e < ENC_; e += 256) {
            float a = 0.f;
#pragma unroll
            for (int ww = 0; ww < 8; ww++) a += accsm[ww][e] * wts[ww];
            g_pacc[(size_t)sid * ENC_ + e] = a;
        }

        // ticket: rows complete for batch b
        __threadfence();
        __syncthreads();
        if (tid == 0) {
            unsigned done = atomicAdd(&g_cnt[b], (unsigned)nrows) + (unsigned)nrows;
            is_last = (done == (unsigned)S_);
        }
        __syncthreads();

        if (is_last) {
            __threadfence();
            const int ns = (int)g_ns[b];              // all flushed (ticket ordering)
            float Mg = -1e30f;
            for (int cc = 0; cc < ns; cc++) Mg = fmaxf(Mg, g_pm[b * MAXSLOT + cc]);
            float Lg = 0.f;
            for (int cc = 0; cc < ns; cc++)
                Lg += g_pl[b * MAXSLOT + cc] * __expf(g_pm[b * MAXSLOT + cc] - Mg);
            const float invL = 1.f / Lg;

            const float* lg = g_logits + b * S_;
            float* attn_out = out + (size_t)b * S_;
            for (int s = tid; s < S_; s += 256)
                attn_out[s] = __expf(lg[s] - Mg) * invL;

            float* sum_out = out + (size_t)B_ * S_ + (size_t)b * ENC_;
            for (int e = tid; e < ENC_; e += 256) {
                float a = 0.f;
                for (int cc = 0; cc < ns; cc++)
                    a += g_pacc[(size_t)(b * MAXSLOT + cc) * ENC_ + e]
                         * __expf(g_pm[b * MAXSLOT + cc] - Mg);
                sum_out[e] = a * invL;
            }
        }

        row = segend;
    }
}

// ============================================================
extern "C" void kernel_launch(void* const* d_in, const int* in_sizes, int n_in,
                              void* d_out, int out_size) {
    const float* dec = (const float*)d_in[0];  // [64,1,512]
    const float* enc = (const float*)d_in[1];  // [64,4096,512]
    const float* W   = (const float*)d_in[2];  // [512,512]
    float* out = (float*)d_out;

    sub_kernel<<<dim3(ENC_ / 64, B_), 256>>>(dec, W);
    attn_pass1<<<NCTA, 256>>>(enc, out);
}